// round 17
// baseline (speedup 1.0000x reference)
#include <cuda_runtime.h>

// Problem constants
#define KC   512          // codebook size
#define DC   16           // channels
#define SV   131072       // T*H*W = 32*64*64 (per-batch spatial)  == 1<<17
#define NPOS 262144       // B * SV
#define QOUT_ELEMS 4194304

// ---- packed f32x2 helpers (sm_100+) ----
__device__ __forceinline__ unsigned long long pk2(float lo, float hi) {
    unsigned long long r;
    asm("mov.b64 %0, {%1, %2};" : "=l"(r) : "f"(lo), "f"(hi));
    return r;
}
__device__ __forceinline__ void unpk2(unsigned long long v, float& lo, float& hi) {
    asm("mov.b64 {%0, %1}, %2;" : "=f"(lo), "=f"(hi) : "l"(v));
}
__device__ __forceinline__ void fma2(unsigned long long& d, unsigned long long a, unsigned long long b) {
    asm("fma.rn.f32x2 %0, %1, %2, %3;" : "=l"(d) : "l"(a), "l"(b), "l"(d));
}

// NEON-style 16-element sum of squares: VF=4 strided lane partials
// (mul-then-add, no fma), then pairwise horizontal (l0+l1)+(l2+l3).
__device__ __forceinline__ float sumsq16_neon(const float* v) {
    float l0 = __fmul_rn(v[0], v[0]);
    float l1 = __fmul_rn(v[1], v[1]);
    float l2 = __fmul_rn(v[2], v[2]);
    float l3 = __fmul_rn(v[3], v[3]);
    #pragma unroll
    for (int i = 1; i < 4; i++) {
        l0 = __fadd_rn(l0, __fmul_rn(v[4*i + 0], v[4*i + 0]));
        l1 = __fadd_rn(l1, __fmul_rn(v[4*i + 1], v[4*i + 1]));
        l2 = __fadd_rn(l2, __fmul_rn(v[4*i + 2], v[4*i + 2]));
        l3 = __fadd_rn(l3, __fmul_rn(v[4*i + 3], v[4*i + 3]));
    }
    return __fadd_rn(__fadd_rn(l0, l1), __fadd_rn(l2, l3));
}

// lane that stored the zero covering column ir during the float4 fill:
// head cols 0..2 -> lanes 0..2; tail col 511 -> lane 31;
// cols 3..510 -> float4 index q=(ir-3)>>2, stored by lane q&31.
__device__ __forceinline__ int owner_lane(int ir) {
    return (ir < 3) ? ir : ((ir >= 511) ? 31 : (((ir - 3) >> 2) & 31));
}

__global__ void vq_init_loss(float* out) {
    if (threadIdx.x == 0) out[0] = 0.0f;
}

// R15 structure (2 pos/thread, 4 codes/iter, select argmin, pipelined fill)
// with ONE change: the pipelined zero-fill uses STG.128 (rows are 16B-aligned
// from element 3) -> 3 store instrs/iter instead of 8.
__global__ __launch_bounds__(256, 2)
void vq_kernel(const float* __restrict__ x, const float* __restrict__ E,
               float* __restrict__ out)
{
    // Packed codebook: Epk[p*8+q] = {E[2p][2q], E[2p+1][2q], E[2p][2q+1], E[2p+1][2q+1]}
    __shared__ float4 Epk[2048];      // 32 KB
    __shared__ float  Se[KC];         // 2 KB  (||e_k||^2, NEON lane+tree order), 16B-aligned
    __shared__ float  wsum[8];

    const int tid = threadIdx.x;

    for (int f = tid; f < 2048; f += 256) {
        int p  = f >> 3, q = f & 7;
        int k0 = p << 1, i0 = q << 1;
        Epk[f] = make_float4(E[k0 * DC + i0],     E[(k0 + 1) * DC + i0],
                             E[k0 * DC + i0 + 1], E[(k0 + 1) * DC + i0 + 1]);
    }
    for (int k = tid; k < KC; k += 256) {
        float er[16];
        #pragma unroll
        for (int i = 0; i < DC; i++) er[i] = E[k * DC + i];
        Se[k] = sumsq16_neon(er);
    }

    const int n0 = blockIdx.x * 512 + tid;     // position ids: n0, n0+256
    const int b0 = n0 >> 17,         s0 = n0 & (SV - 1);
    const int b1 = (n0 + 256) >> 17, s1 = (n0 + 256) & (SV - 1);

    unsigned long long xx0[16], xx1[16];
    float Sx0, Sx1;
    {
        float xs0[16], xs1[16];
        #pragma unroll
        for (int c = 0; c < DC; c++) {
            float v0 = x[(((b0 << 4) + c) << 17) + s0];
            float v1 = x[(((b1 << 4) + c) << 17) + s1];
            xs0[c] = v0; xx0[c] = pk2(v0, v0);
            xs1[c] = v1; xx1[c] = pk2(v1, v1);
        }
        // ||x||^2 in NEON lane+tree order (XLA:CPU vectorized row-reduce).
        Sx0 = sumsq16_neon(xs0);
        Sx1 = sumsq16_neon(xs1);
    }   // xs dead here -> registers freed before the main loop

    float* __restrict__ qout = out + 1;
    float* __restrict__ enc  = out + 1 + QOUT_ELEMS;
    const int lane  = tid & 31;
    const int wbase = blockIdx.x * 512 + (tid & ~31);

    __syncthreads();   // Epk/Se ready

    // Argmin over 512 codes: 4 codes x 2 positions per iteration =
    // 4 independent packed-FMA chains. Each iteration ALSO issues this
    // warp's slice of the encodings zero-fill (one row per 2 iterations,
    // STG.128 bulk: row base == 4 mod 16, so row+3 is 16B-aligned).
    // The later 1.0 write to row[ir] is issued post-loop by the SAME lane
    // (owner_lane) that stored the zero covering that column -> same-thread
    // program order keeps it ordered after the zero.
    //
    // dot per (pos,code): SINGLE sequential ascending FMA chain from 0 —
    // bit-identical to Eigen gemm k-loop accumulation (aarch64 vfmaq).
    // dist = fl( fl(Sx + Se_k) - 2*dot_k ): fma(-2,dot,t) rounds once,
    // identical to the reference's subtract (2*dot exact).
    // Strict < keeps first-index ties.
    float bestd0 = 3.402823466e38f, bestd1 = 3.402823466e38f;
    int   besti0 = 0,               besti1 = 0;
    const float4 z4 = make_float4(0.f, 0.f, 0.f, 0.f);
    #pragma unroll 2
    for (int pp = 0; pp < 128; pp++) {
        // -- pipelined zero-fill slice: row (pp>>1), half (pp&1) --
        {
            int r = pp >> 1;                        // 0..63
            float* row = enc + (long)(wbase + ((r & 1) << 8) + (r >> 1)) * KC;
            if ((pp & 1) == 0) {
                if (lane < 3) row[lane] = 0.0f;     // head scalars 0..2
                *reinterpret_cast<float4*>(row + 3 + 4 * lane)        = z4;  // q=lane
                *reinterpret_cast<float4*>(row + 3 + 4 * (lane + 32)) = z4;  // q=lane+32
            } else {
                *reinterpret_cast<float4*>(row + 3 + 4 * (lane + 64)) = z4;  // q=lane+64
                if (lane < 31)
                    *reinterpret_cast<float4*>(row + 3 + 4 * (lane + 96)) = z4; // q=lane+96
                else
                    row[511] = 0.0f;                // tail scalar (lane 31)
            }
        }

        const ulonglong2* ep = reinterpret_cast<const ulonglong2*>(Epk + (pp << 4));
        unsigned long long a0 = 0ULL, a1 = 0ULL, bb0 = 0ULL, bb1 = 0ULL;
        #pragma unroll
        for (int q = 0; q < 8; q++) {
            ulonglong2 ea = ep[q];        // pair 2pp   (codes 4pp, 4pp+1)
            ulonglong2 eb = ep[q + 8];    // pair 2pp+1 (codes 4pp+2, 4pp+3)
            fma2(a0,  xx0[2 * q],     ea.x);
            fma2(a1,  xx1[2 * q],     ea.x);
            fma2(bb0, xx0[2 * q],     eb.x);
            fma2(bb1, xx1[2 * q],     eb.x);
            fma2(a0,  xx0[2 * q + 1], ea.y);
            fma2(a1,  xx1[2 * q + 1], ea.y);
            fma2(bb0, xx0[2 * q + 1], eb.y);
            fma2(bb1, xx1[2 * q + 1], eb.y);
        }
        const float4 se = *reinterpret_cast<const float4*>(&Se[pp << 2]);
        const int k0 = pp << 2;

        float dlo, dhi, d;
        // pos0, codes k0..k0+3 ascending (strict <: first-index ties)
        unpk2(a0, dlo, dhi);
        d = __fmaf_rn(-2.0f, dlo, __fadd_rn(Sx0, se.x));
        if (d < bestd0) { bestd0 = d; besti0 = k0; }
        d = __fmaf_rn(-2.0f, dhi, __fadd_rn(Sx0, se.y));
        if (d < bestd0) { bestd0 = d; besti0 = k0 + 1; }
        unpk2(bb0, dlo, dhi);
        d = __fmaf_rn(-2.0f, dlo, __fadd_rn(Sx0, se.z));
        if (d < bestd0) { bestd0 = d; besti0 = k0 + 2; }
        d = __fmaf_rn(-2.0f, dhi, __fadd_rn(Sx0, se.w));
        if (d < bestd0) { bestd0 = d; besti0 = k0 + 3; }
        // pos1
        unpk2(a1, dlo, dhi);
        d = __fmaf_rn(-2.0f, dlo, __fadd_rn(Sx1, se.x));
        if (d < bestd1) { bestd1 = d; besti1 = k0; }
        d = __fmaf_rn(-2.0f, dhi, __fadd_rn(Sx1, se.y));
        if (d < bestd1) { bestd1 = d; besti1 = k0 + 1; }
        unpk2(bb1, dlo, dhi);
        d = __fmaf_rn(-2.0f, dlo, __fadd_rn(Sx1, se.z));
        if (d < bestd1) { bestd1 = d; besti1 = k0 + 2; }
        d = __fmaf_rn(-2.0f, dhi, __fadd_rn(Sx1, se.w));
        if (d < bestd1) { bestd1 = d; besti1 = k0 + 3; }
    }

    // ---- encodings 1.0 writes (owner lane; zeros issued in the loop) ----
    #pragma unroll 1
    for (int r = 0; r < 32; r++) {
        int ir0 = __shfl_sync(0xffffffffu, besti0, r);
        int ir1 = __shfl_sync(0xffffffffu, besti1, r);
        if (lane == owner_lane(ir0)) enc[(long)(wbase + r) * KC + ir0] = 1.0f;
        if (lane == owner_lane(ir1)) enc[(long)(wbase + 256 + r) * KC + ir1] = 1.0f;
    }

    // ---- q_out (straight-through emulation) + loss partial ----
    float lsum = 0.0f;
    const float* __restrict__ Er0 = E + besti0 * DC;
    const float* __restrict__ Er1 = E + besti1 * DC;
    #pragma unroll
    for (int c = 0; c < DC; c++) {
        float v0, v1, dummy;
        unpk2(xx0[c], v0, dummy);
        unpk2(xx1[c], v1, dummy);
        float q0 = Er0[c];
        float df0 = __fsub_rn(q0, v0);           // fl(q - x)
        lsum = __fmaf_rn(df0, df0, lsum);
        qout[(((b0 << 4) + c) << 17) + s0] = __fadd_rn(v0, df0);

        float q1 = Er1[c];
        float df1 = __fsub_rn(q1, v1);
        lsum = __fmaf_rn(df1, df1, lsum);
        qout[(((b1 << 4) + c) << 17) + s1] = __fadd_rn(v1, df1);
    }

    // reduce loss: warp -> block -> one atomicAdd per block
    #pragma unroll
    for (int o = 16; o > 0; o >>= 1)
        lsum += __shfl_xor_sync(0xffffffffu, lsum, o);
    if (lane == 0) wsum[tid >> 5] = lsum;
    __syncthreads();
    if (tid == 0) {
        float t = 0.0f;
        #pragma unroll
        for (int w = 0; w < 8; w++) t += wsum[w];
        // loss = q_latent + 0.25*e_latent = 1.25 * mean((q - x)^2)
        atomicAdd(out, t * (1.25f / (float)(NPOS * DC)));
    }
}

extern "C" void kernel_launch(void* const* d_in, const int* in_sizes, int n_in,
                              void* d_out, int out_size)
{
    const float* x = (const float*)d_in[0];
    const float* E = (const float*)d_in[1];
    float* out = (float*)d_out;

    vq_init_loss<<<1, 32>>>(out);
    vq_kernel<<<NPOS / 512, 256>>>(x, E, out);
}